// round 1
// baseline (speedup 1.0000x reference)
#include <cuda_runtime.h>
#include <cstdint>

#define BATCH 8192
#define NH    16
#define HD    256
#define FH    512

// ---------------- scratch (static device arrays; no allocations) ------------
__device__ float g_p[(size_t)BATCH * NH * HD];    // residual input to FFN
__device__ float g_h[(size_t)BATCH * NH * HD];    // rmsnorm2 output (GEMM A)
__device__ float g_gate[(size_t)BATCH * NH * FH]; // silu(h@w1)*(h@w3)

// ---------------- packed f32x2 FMA (FFMA2) ----------------------------------
__device__ __forceinline__ void ffma2(unsigned long long& c,
                                      unsigned long long a,
                                      unsigned long long b) {
    asm("fma.rn.f32x2 %0, %1, %2, %0;" : "+l"(c) : "l"(a), "l"(b));
}

__device__ __forceinline__ float2 u2f(unsigned long long v) {
    float2 r;
    asm("mov.b64 {%0, %1}, %2;" : "=f"(r.x), "=f"(r.y) : "l"(v));
    return r;
}

// ---------------- kernel 1: rmsnorm1 -> headmix*mask + x -> rmsnorm2 --------
// one block per token, 16 warps = 16 heads
__global__ __launch_bounds__(512) void mix_kernel(
    const float* __restrict__ x,
    const float* __restrict__ n1w,
    const float* __restrict__ n2w,
    const float* __restrict__ mask)
{
    __shared__ float xn[16 * 272];   // 272-float row pitch: conflict-free mix reads

    const int b    = blockIdx.x;
    const int w    = threadIdx.x >> 5;   // head
    const int lane = threadIdx.x & 31;

    const float* xb = x + ((size_t)b * NH + w) * HD;

    // phase 1: rmsnorm1 for head w
    float v[8];
    float ss = 0.f;
#pragma unroll
    for (int q = 0; q < 8; q++) {
        v[q] = xb[lane + 32 * q];
        ss += v[q] * v[q];
    }
#pragma unroll
    for (int o = 16; o > 0; o >>= 1) ss += __shfl_xor_sync(0xffffffffu, ss, o);
    float rms = rsqrtf(ss * (1.f / HD) + 1e-6f);
#pragma unroll
    for (int q = 0; q < 8; q++) {
        int d = lane + 32 * q;
        xn[w * 272 + d] = v[q] * rms * n1w[d];
    }
    __syncthreads();

    // phase 2: mixed[b, i=w, d] = xn[j, i*16+t] * mask[i,d] + x[b,i,d]; then rmsnorm2
    float p[8];
    float ps = 0.f;
#pragma unroll
    for (int q = 0; q < 8; q++) {
        int d = lane + 32 * q;
        int j = d >> 4;
        int t = d & 15;
        float mixed = xn[j * 272 + (w << 4) + t] * mask[w * HD + d];
        float pv = mixed + v[q];     // v[q] == x[b,w,d] (same load pattern)
        p[q] = pv;
        ps += pv * pv;
    }
#pragma unroll
    for (int o = 16; o > 0; o >>= 1) ps += __shfl_xor_sync(0xffffffffu, ps, o);
    float rms2 = rsqrtf(ps * (1.f / HD) + 1e-6f);

    const size_t base = ((size_t)b * NH + w) * HD;
#pragma unroll
    for (int q = 0; q < 8; q++) {
        int d = lane + 32 * q;
        g_p[base + d] = p[q];
        g_h[base + d] = p[q] * rms2 * n2w[d];
    }
}

// ---------------- kernel 2: per-head  A=H@W1, B=H@W3, G=silu(A)*B -----------
// block tile: 64 tokens x 128 hidden; threads 256 (16x16), thread tile 4m x 8n
__global__ __launch_bounds__(256) void ffn1_kernel(
    const float* __restrict__ w1,
    const float* __restrict__ w3)
{
    __shared__ float Hs[32 * 130];   // K-major, A duplicated: Hs[k][2m],[2m+1]
    __shared__ float W1s[32 * 128];
    __shared__ float W3s[32 * 128];

    const int head = blockIdx.z;
    const int b0   = blockIdx.x * 64;
    const int n0   = blockIdx.y * 128;
    const int tid  = threadIdx.x;
    const int tyA  = tid >> 4;   // 0..15 -> 4 m-rows each
    const int txA  = tid & 15;   // 0..15 -> n cols {txA*4..+3} U {64+txA*4..+3}

    unsigned long long accA[4][4], accB[4][4];
#pragma unroll
    for (int i = 0; i < 4; i++)
#pragma unroll
        for (int j = 0; j < 4; j++) { accA[i][j] = 0ull; accB[i][j] = 0ull; }

    // loader roles
    const int lm = tid >> 2;            // 0..63 token row
    const int lk = (tid & 3) * 8;       // k segment
    const float* hsrc = g_h + ((size_t)(b0 + lm) * NH + head) * HD + lk;
    const int wk = tid >> 3;            // 0..31 k row
    const int wn = (tid & 7) * 16;      // n segment
    const float* w1src = w1 + ((size_t)head * HD + wk) * FH + n0 + wn;
    const float* w3src = w3 + ((size_t)head * HD + wk) * FH + n0 + wn;

    for (int k0 = 0; k0 < HD; k0 += 32) {
        float4 hv0 = *(const float4*)(hsrc + k0);
        float4 hv1 = *(const float4*)(hsrc + k0 + 4);
        {
            float* hrow;
            hrow = &Hs[(lk + 0) * 130 + 2 * lm]; hrow[0] = hv0.x; hrow[1] = hv0.x;
            hrow = &Hs[(lk + 1) * 130 + 2 * lm]; hrow[0] = hv0.y; hrow[1] = hv0.y;
            hrow = &Hs[(lk + 2) * 130 + 2 * lm]; hrow[0] = hv0.z; hrow[1] = hv0.z;
            hrow = &Hs[(lk + 3) * 130 + 2 * lm]; hrow[0] = hv0.w; hrow[1] = hv0.w;
            hrow = &Hs[(lk + 4) * 130 + 2 * lm]; hrow[0] = hv1.x; hrow[1] = hv1.x;
            hrow = &Hs[(lk + 5) * 130 + 2 * lm]; hrow[0] = hv1.y; hrow[1] = hv1.y;
            hrow = &Hs[(lk + 6) * 130 + 2 * lm]; hrow[0] = hv1.z; hrow[1] = hv1.z;
            hrow = &Hs[(lk + 7) * 130 + 2 * lm]; hrow[0] = hv1.w; hrow[1] = hv1.w;
        }
#pragma unroll
        for (int j = 0; j < 4; j++) {
            *(float4*)&W1s[wk * 128 + wn + 4 * j] =
                *(const float4*)(w1src + (size_t)k0 * FH + 4 * j);
            *(float4*)&W3s[wk * 128 + wn + 4 * j] =
                *(const float4*)(w3src + (size_t)k0 * FH + 4 * j);
        }
        __syncthreads();

#pragma unroll 8
        for (int kk = 0; kk < 32; kk++) {
            unsigned long long a[4];
#pragma unroll
            for (int mi = 0; mi < 4; mi++)
                a[mi] = *(const unsigned long long*)&Hs[kk * 130 + tyA * 8 + 2 * mi];
            ulonglong2 p1l = *(const ulonglong2*)&W1s[kk * 128 + txA * 4];
            ulonglong2 p1h = *(const ulonglong2*)&W1s[kk * 128 + 64 + txA * 4];
            ulonglong2 p3l = *(const ulonglong2*)&W3s[kk * 128 + txA * 4];
            ulonglong2 p3h = *(const ulonglong2*)&W3s[kk * 128 + 64 + txA * 4];
#pragma unroll
            for (int mi = 0; mi < 4; mi++) {
                ffma2(accA[mi][0], a[mi], p1l.x);
                ffma2(accA[mi][1], a[mi], p1l.y);
                ffma2(accA[mi][2], a[mi], p1h.x);
                ffma2(accA[mi][3], a[mi], p1h.y);
                ffma2(accB[mi][0], a[mi], p3l.x);
                ffma2(accB[mi][1], a[mi], p3l.y);
                ffma2(accB[mi][2], a[mi], p3h.x);
                ffma2(accB[mi][3], a[mi], p3h.y);
            }
        }
        __syncthreads();
    }

    // epilogue: G = silu(A) * B
    float* gdst = g_gate + ((size_t)(b0 + tyA * 4) * NH + head) * FH + n0;
#pragma unroll
    for (int mi = 0; mi < 4; mi++) {
        float* row = gdst + (size_t)mi * NH * FH;
#pragma unroll
        for (int h = 0; h < 4; h++) {
            float2 av = u2f(accA[mi][h]);
            float2 bv = u2f(accB[mi][h]);
            float2 g;
            g.x = av.x / (1.f + __expf(-av.x)) * bv.x;
            g.y = av.y / (1.f + __expf(-av.y)) * bv.y;
            int col = (h < 2) ? (txA * 4 + 2 * h) : (64 + txA * 4 + 2 * (h - 2));
            *(float2*)(row + col) = g;
        }
    }
}

// ---------------- kernel 3: OUT = G @ W2 + P --------------------------------
__global__ __launch_bounds__(256) void ffn2_kernel(
    const float* __restrict__ w2,
    float* __restrict__ out)
{
    __shared__ float Gs[32 * 130];
    __shared__ float W2s[32 * 128];

    const int head = blockIdx.z;
    const int b0   = blockIdx.x * 64;
    const int n0   = blockIdx.y * 128;
    const int tid  = threadIdx.x;
    const int tyA  = tid >> 4;
    const int txA  = tid & 15;

    unsigned long long acc[4][4];
#pragma unroll
    for (int i = 0; i < 4; i++)
#pragma unroll
        for (int j = 0; j < 4; j++) acc[i][j] = 0ull;

    const int lm = tid >> 2;
    const int lk = (tid & 3) * 8;
    const float* gsrc = g_gate + ((size_t)(b0 + lm) * NH + head) * FH + lk;
    const int wk = tid >> 3;
    const int wn = (tid & 7) * 16;
    const float* w2src = w2 + ((size_t)head * FH + wk) * HD + n0 + wn;

    for (int k0 = 0; k0 < FH; k0 += 32) {
        float4 gv0 = *(const float4*)(gsrc + k0);
        float4 gv1 = *(const float4*)(gsrc + k0 + 4);
        {
            float* grow;
            grow = &Gs[(lk + 0) * 130 + 2 * lm]; grow[0] = gv0.x; grow[1] = gv0.x;
            grow = &Gs[(lk + 1) * 130 + 2 * lm]; grow[0] = gv0.y; grow[1] = gv0.y;
            grow = &Gs[(lk + 2) * 130 + 2 * lm]; grow[0] = gv0.z; grow[1] = gv0.z;
            grow = &Gs[(lk + 3) * 130 + 2 * lm]; grow[0] = gv0.w; grow[1] = gv0.w;
            grow = &Gs[(lk + 4) * 130 + 2 * lm]; grow[0] = gv1.x; grow[1] = gv1.x;
            grow = &Gs[(lk + 5) * 130 + 2 * lm]; grow[0] = gv1.y; grow[1] = gv1.y;
            grow = &Gs[(lk + 6) * 130 + 2 * lm]; grow[0] = gv1.z; grow[1] = gv1.z;
            grow = &Gs[(lk + 7) * 130 + 2 * lm]; grow[0] = gv1.w; grow[1] = gv1.w;
        }
#pragma unroll
        for (int j = 0; j < 4; j++) {
            *(float4*)&W2s[wk * 128 + wn + 4 * j] =
                *(const float4*)(w2src + (size_t)k0 * HD + 4 * j);
        }
        __syncthreads();

#pragma unroll 8
        for (int kk = 0; kk < 32; kk++) {
            unsigned long long a[4];
#pragma unroll
            for (int mi = 0; mi < 4; mi++)
                a[mi] = *(const unsigned long long*)&Gs[kk * 130 + tyA * 8 + 2 * mi];
            ulonglong2 pl = *(const ulonglong2*)&W2s[kk * 128 + txA * 4];
            ulonglong2 ph = *(const ulonglong2*)&W2s[kk * 128 + 64 + txA * 4];
#pragma unroll
            for (int mi = 0; mi < 4; mi++) {
                ffma2(acc[mi][0], a[mi], pl.x);
                ffma2(acc[mi][1], a[mi], pl.y);
                ffma2(acc[mi][2], a[mi], ph.x);
                ffma2(acc[mi][3], a[mi], ph.y);
            }
        }
        __syncthreads();
    }

    // epilogue: out = acc + p
    const size_t rbase = ((size_t)(b0 + tyA * 4) * NH + head) * HD + n0;
#pragma unroll
    for (int mi = 0; mi < 4; mi++) {
        const size_t roff = rbase + (size_t)mi * NH * HD;
#pragma unroll
        for (int h = 0; h < 4; h++) {
            int col = (h < 2) ? (txA * 4 + 2 * h) : (64 + txA * 4 + 2 * (h - 2));
            float2 c = u2f(acc[mi][h]);
            float2 pv = *(const float2*)(g_p + roff + col);
            c.x += pv.x;
            c.y += pv.y;
            *(float2*)(out + roff + col) = c;
        }
    }
}

// ---------------- launcher --------------------------------------------------
extern "C" void kernel_launch(void* const* d_in, const int* in_sizes, int n_in,
                              void* d_out, int out_size)
{
    const float* x    = (const float*)d_in[0];
    const float* n1w  = (const float*)d_in[1];
    const float* n2w  = (const float*)d_in[2];
    const float* w1   = (const float*)d_in[3];
    const float* w3   = (const float*)d_in[4];
    const float* w2   = (const float*)d_in[5];
    const float* mask = (const float*)d_in[6];
    float* out = (float*)d_out;

    mix_kernel<<<BATCH, 512>>>(x, n1w, n2w, mask);
    ffn1_kernel<<<dim3(BATCH / 64, FH / 128, NH), 256>>>(w1, w3);
    ffn2_kernel<<<dim3(BATCH / 64, HD / 128, NH), 256>>>(w2, out);
}

// round 4
// speedup vs baseline: 4.0579x; 4.0579x over previous
#include <cuda_runtime.h>
#include <cstdint>

#define BATCH 8192
#define NH    16
#define HD    256
#define FH    512

// ---------------- scratch (static device arrays; no allocations) ------------
__device__ float g_p[(size_t)NH * BATCH * HD];     // residual, head-major
__device__ float g_h[(size_t)NH * BATCH * HD];     // rmsnorm2 out (tf32-rounded)
__device__ float g_a[(size_t)NH * BATCH * FH];     // h@w1 raw
__device__ float g_gate[(size_t)NH * BATCH * FH];  // silu(a)*b (tf32-rounded)
__device__ float g_w1t[(size_t)NH * FH * HD];      // [h][n=512][k=256]
__device__ float g_w3t[(size_t)NH * FH * HD];
__device__ float g_w2t[(size_t)NH * HD * FH];      // [h][n=256][k=512]

// ---------------- PTX helpers -----------------------------------------------
__device__ __forceinline__ uint32_t smem_u32(const void* p) {
    uint32_t a;
    asm("{ .reg .u64 t; cvta.to.shared.u64 t, %1; cvt.u32.u64 %0, t; }" : "=r"(a) : "l"(p));
    return a;
}
__device__ __forceinline__ float tf32r(float x) {
    float r;
    asm("cvt.rna.tf32.f32 %0, %1;" : "=f"(r) : "f"(x));
    return r;
}
__device__ __forceinline__ void cp16(uint32_t d, const void* s) {
    asm volatile("cp.async.cg.shared.global [%0], [%1], 16;" :: "r"(d), "l"(s));
}
__device__ __forceinline__ void cp_commit() {
    asm volatile("cp.async.commit_group;" ::: "memory");
}
template<int N> __device__ __forceinline__ void cp_wait() {
    asm volatile("cp.async.wait_group %0;" :: "n"(N) : "memory");
}
__device__ __forceinline__ void ldsm4(uint32_t* r, uint32_t a) {
    asm volatile("ldmatrix.sync.aligned.m8n8.x4.shared.b16 {%0,%1,%2,%3}, [%4];"
                 : "=r"(r[0]), "=r"(r[1]), "=r"(r[2]), "=r"(r[3]) : "r"(a));
}
__device__ __forceinline__ void mma8(float* c, const uint32_t* a, uint32_t b0, uint32_t b1) {
    asm volatile(
        "mma.sync.aligned.m16n8k8.row.col.f32.tf32.tf32.f32 "
        "{%0,%1,%2,%3}, {%4,%5,%6,%7}, {%8,%9}, {%0,%1,%2,%3};"
        : "+f"(c[0]), "+f"(c[1]), "+f"(c[2]), "+f"(c[3])
        : "r"(a[0]), "r"(a[1]), "r"(a[2]), "r"(a[3]), "r"(b0), "r"(b1));
}

// ---------------- kernel 0: weight transposes + tf32 rounding ---------------
__global__ __launch_bounds__(256) void transpose_kernel(
    const float* __restrict__ w1, const float* __restrict__ w3,
    const float* __restrict__ w2)
{
    __shared__ float s[32][33];
    const int zz = blockIdx.z;
    const int tensor = zz >> 4, head = zz & 15;
    const float* src;
    float* dst;
    int R, C;
    if (tensor == 0)      { src = w1 + (size_t)head * HD * FH; dst = g_w1t + (size_t)head * FH * HD; R = HD; C = FH; }
    else if (tensor == 1) { src = w3 + (size_t)head * HD * FH; dst = g_w3t + (size_t)head * FH * HD; R = HD; C = FH; }
    else                  { src = w2 + (size_t)head * FH * HD; dst = g_w2t + (size_t)head * HD * FH; R = FH; C = HD; }

    const int r0 = blockIdx.y * 32, c0 = blockIdx.x * 32;
    if (r0 >= R || c0 >= C) return;
    const int tx = threadIdx.x & 31, ty = threadIdx.x >> 5;
#pragma unroll
    for (int j = 0; j < 4; j++)
        s[ty + 8 * j][tx] = src[(size_t)(r0 + ty + 8 * j) * C + c0 + tx];
    __syncthreads();
#pragma unroll
    for (int j = 0; j < 4; j++)
        dst[(size_t)(c0 + ty + 8 * j) * R + r0 + tx] = tf32r(s[tx][ty + 8 * j]);
}

// ---------------- kernel 1: rmsnorm1 -> headmix*mask + x -> rmsnorm2 --------
__global__ __launch_bounds__(512) void mix_kernel(
    const float* __restrict__ x,
    const float* __restrict__ n1w,
    const float* __restrict__ n2w,
    const float* __restrict__ mask)
{
    __shared__ float xn[16 * 272];

    const int b    = blockIdx.x;
    const int w    = threadIdx.x >> 5;
    const int lane = threadIdx.x & 31;

    const float* xb = x + ((size_t)b * NH + w) * HD;

    float v[8];
    float ss = 0.f;
#pragma unroll
    for (int q = 0; q < 8; q++) {
        v[q] = xb[lane + 32 * q];
        ss += v[q] * v[q];
    }
#pragma unroll
    for (int o = 16; o > 0; o >>= 1) ss += __shfl_xor_sync(0xffffffffu, ss, o);
    float rms = rsqrtf(ss * (1.f / HD) + 1e-6f);
#pragma unroll
    for (int q = 0; q < 8; q++) {
        int d = lane + 32 * q;
        xn[w * 272 + d] = v[q] * rms * n1w[d];
    }
    __syncthreads();

    float p[8];
    float ps = 0.f;
#pragma unroll
    for (int q = 0; q < 8; q++) {
        int d = lane + 32 * q;
        int j = d >> 4;
        int t = d & 15;
        float mixed = xn[j * 272 + (w << 4) + t] * mask[w * HD + d];
        float pv = mixed + v[q];
        p[q] = pv;
        ps += pv * pv;
    }
#pragma unroll
    for (int o = 16; o > 0; o >>= 1) ps += __shfl_xor_sync(0xffffffffu, ps, o);
    float rms2 = rsqrtf(ps * (1.f / HD) + 1e-6f);

    const size_t base = ((size_t)w * BATCH + b) * HD;   // head-major
#pragma unroll
    for (int q = 0; q < 8; q++) {
        int d = lane + 32 * q;
        g_p[base + d] = p[q];
        g_h[base + d] = tf32r(p[q] * rms2 * n2w[d]);
    }
}

// ---------------- GEMM kernels: mma.sync tf32, 128x128 CTA, K-tile 32 -------
// MODE 0: g_a    = H @ W1                (per head)
// MODE 1: g_gate = tf32(silu(g_a) * (H @ W3))
// MODE 2: out    = G @ W2 + g_p          (token-major out)
template<int MODE>
__global__ __launch_bounds__(256, 2) void gemm_kernel(float* __restrict__ outp)
{
    constexpr int LDA = (MODE == 2) ? FH : HD;   // K dim
    constexpr int KT  = LDA / 32;                // 8 or 16 k-tiles
    extern __shared__ char smem[];
    const uint32_t sbase = smem_u32(smem);

    const int head = blockIdx.z;
    const int b0 = blockIdx.x * 128;
    const int n0 = blockIdx.y * 128;
    const int tid = threadIdx.x;

    const float* Ag = (MODE == 2 ? g_gate : g_h)
                    + (size_t)head * BATCH * LDA + (size_t)b0 * LDA;
    const float* Bg = (MODE == 0 ? g_w1t : MODE == 1 ? g_w3t : g_w2t)
                    + (size_t)head * FH * HD + (size_t)n0 * LDA;

    // ---- loader precompute: 4 rows each for A and B tiles (128 x 32 fl) ----
    const int lrow = tid >> 3;
    const int lq   = tid & 7;
    uint32_t adst[4], bdst[4];
    const float* asrc[4];
    const float* bsrc[4];
#pragma unroll
    for (int t = 0; t < 4; t++) {
        int r = lrow + 32 * t;
        uint32_t sw = ((uint32_t)(lq ^ (r & 7))) << 4;
        adst[t] = (uint32_t)r * 128 + sw;
        bdst[t] = adst[t];
        asrc[t] = Ag + (size_t)r * LDA + lq * 4;
        bsrc[t] = Bg + (size_t)r * LDA + lq * 4;
    }

    // ---- compute precompute ----
    const int lane = tid & 31, warp = tid >> 5;
    const int wm = warp & 1, wn = warp >> 1;   // warp tile 64(M) x 32(N)
    uint32_t aoff[4], boff[2];
    {
        int rb = wm * 64 + (lane & 15);
        int aq = lane >> 4;
#pragma unroll
        for (int mi = 0; mi < 4; mi++) {
            int r = rb + 16 * mi;
            aoff[mi] = (uint32_t)r * 128 + ((uint32_t)(aq ^ (r & 7)) << 4);
        }
#pragma unroll
        for (int p = 0; p < 2; p++) {
            int r = wn * 32 + p * 16 + (lane & 7) + ((lane & 16) ? 8 : 0);
            int bq = (lane >> 3) & 1;
            boff[p] = (uint32_t)r * 128 + ((uint32_t)(bq ^ (r & 7)) << 4);
        }
    }

    float acc[16][4];
#pragma unroll
    for (int i = 0; i < 16; i++)
#pragma unroll
        for (int j = 0; j < 4; j++) acc[i][j] = 0.f;

    // ---- pipelined main loop ----
    auto load_tile = [&](int kt, int buf) {
        uint32_t s = sbase + buf * 32768u;
#pragma unroll
        for (int t = 0; t < 4; t++) cp16(s + adst[t], asrc[t] + kt * 32);
#pragma unroll
        for (int t = 0; t < 4; t++) cp16(s + 16384u + bdst[t], bsrc[t] + kt * 32);
    };

    load_tile(0, 0); cp_commit();
    load_tile(1, 1); cp_commit();

    for (int kt = 0; kt < KT; kt++) {
        if (kt == KT - 1) cp_wait<0>(); else cp_wait<1>();
        __syncthreads();
        uint32_t sA = sbase + (kt & 1) * 32768u;
        uint32_t sB = sA + 16384u;
#pragma unroll
        for (int ks = 0; ks < 4; ks++) {
            uint32_t xo = (uint32_t)ks << 5;
            uint32_t a[4][4], b[2][4];
#pragma unroll
            for (int mi = 0; mi < 4; mi++) ldsm4(a[mi], sA + (aoff[mi] ^ xo));
#pragma unroll
            for (int p = 0; p < 2; p++) ldsm4(b[p], sB + (boff[p] ^ xo));
#pragma unroll
            for (int mi = 0; mi < 4; mi++)
#pragma unroll
                for (int nj = 0; nj < 4; nj++)
                    mma8(acc[mi * 4 + nj], a[mi],
                         b[nj >> 1][(nj & 1) * 2], b[nj >> 1][(nj & 1) * 2 + 1]);
        }
        __syncthreads();
        if (kt + 2 < KT) { load_tile(kt + 2, kt & 1); cp_commit(); }
    }

    // ---- epilogue ----
    const int g = lane >> 2, tg = lane & 3;
#pragma unroll
    for (int mi = 0; mi < 4; mi++) {
#pragma unroll
        for (int nj = 0; nj < 4; nj++) {
            float* d = acc[mi * 4 + nj];
            int row = wm * 64 + mi * 16 + g;          // local m (and +8)
            int col = wn * 32 + nj * 8 + 2 * tg;      // local n

            if (MODE == 0) {
                float* c = g_a + ((size_t)head * BATCH + b0) * FH + n0;
                *(float2*)(c + (size_t)row * FH + col)       = make_float2(d[0], d[1]);
                *(float2*)(c + (size_t)(row + 8) * FH + col) = make_float2(d[2], d[3]);
            } else if (MODE == 1) {
                const float* ax = g_a    + ((size_t)head * BATCH + b0) * FH + n0;
                float*       c  = g_gate + ((size_t)head * BATCH + b0) * FH + n0;
#pragma unroll
                for (int h = 0; h < 2; h++) {
                    float2 av = *(const float2*)(ax + (size_t)(row + 8 * h) * FH + col);
                    float g0 = av.x / (1.f + __expf(-av.x)) * d[2 * h + 0];
                    float g1 = av.y / (1.f + __expf(-av.y)) * d[2 * h + 1];
                    *(float2*)(c + (size_t)(row + 8 * h) * FH + col) =
                        make_float2(tf32r(g0), tf32r(g1));
                }
            } else {
                const float* px = g_p + ((size_t)head * BATCH + b0) * HD + n0;
#pragma unroll
                for (int h = 0; h < 2; h++) {
                    float2 pv = *(const float2*)(px + (size_t)(row + 8 * h) * HD + col);
                    float2 o = make_float2(d[2 * h] + pv.x, d[2 * h + 1] + pv.y);
                    *(float2*)(outp + (size_t)(b0 + row + 8 * h) * NH * HD
                                    + (size_t)head * HD + n0 + col) = o;
                }
            }
        }
    }
}

// ---------------- launcher --------------------------------------------------
extern "C" void kernel_launch(void* const* d_in, const int* in_sizes, int n_in,
                              void* d_out, int out_size)
{
    const float* x    = (const float*)d_in[0];
    const float* n1w  = (const float*)d_in[1];
    const float* n2w  = (const float*)d_in[2];
    const float* w1   = (const float*)d_in[3];
    const float* w3   = (const float*)d_in[4];
    const float* w2   = (const float*)d_in[5];
    const float* mask = (const float*)d_in[6];
    float* out = (float*)d_out;

    cudaFuncSetAttribute(gemm_kernel<0>, cudaFuncAttributeMaxDynamicSharedMemorySize, 65536);
    cudaFuncSetAttribute(gemm_kernel<1>, cudaFuncAttributeMaxDynamicSharedMemorySize, 65536);
    cudaFuncSetAttribute(gemm_kernel<2>, cudaFuncAttributeMaxDynamicSharedMemorySize, 65536);

    transpose_kernel<<<dim3(16, 16, 48), 256>>>(w1, w3, w2);
    mix_kernel<<<BATCH, 512>>>(x, n1w, n2w, mask);
    gemm_kernel<0><<<dim3(BATCH / 128, FH / 128, NH), 256, 65536>>>(nullptr);
    gemm_kernel<1><<<dim3(BATCH / 128, FH / 128, NH), 256, 65536>>>(nullptr);
    gemm_kernel<2><<<dim3(BATCH / 128, HD / 128, NH), 256, 65536>>>(out);
}

// round 5
// speedup vs baseline: 5.3001x; 1.3061x over previous
#include <cuda_runtime.h>
#include <cstdint>

#define BATCH 8192
#define NH    16
#define HD    256
#define FH    512

// ---------------- scratch (static device arrays; no allocations) ------------
__device__ float g_p[(size_t)NH * BATCH * HD];     // residual, head-major
__device__ float g_h[(size_t)NH * BATCH * HD];     // rmsnorm2 out (tf32-rounded)
__device__ float g_gate[(size_t)NH * BATCH * FH];  // silu(h@w1)*(h@w3) (tf32-rounded)
__device__ float g_w1t[(size_t)NH * FH * HD];      // [h][n=512][k=256]
__device__ float g_w3t[(size_t)NH * FH * HD];
__device__ float g_w2t[(size_t)NH * HD * FH];      // [h][n=256][k=512]

// ---------------- PTX helpers -----------------------------------------------
__device__ __forceinline__ uint32_t smem_u32(const void* p) {
    uint32_t a;
    asm("{ .reg .u64 t; cvta.to.shared.u64 t, %1; cvt.u32.u64 %0, t; }" : "=r"(a) : "l"(p));
    return a;
}
__device__ __forceinline__ float tf32r(float x) {
    float r;
    asm("cvt.rna.tf32.f32 %0, %1;" : "=f"(r) : "f"(x));
    return r;
}
__device__ __forceinline__ void cp16(uint32_t d, const void* s) {
    asm volatile("cp.async.cg.shared.global [%0], [%1], 16;" :: "r"(d), "l"(s));
}
__device__ __forceinline__ void cp_commit() {
    asm volatile("cp.async.commit_group;" ::: "memory");
}
template<int N> __device__ __forceinline__ void cp_wait() {
    asm volatile("cp.async.wait_group %0;" :: "n"(N) : "memory");
}
__device__ __forceinline__ void ldsm4(uint32_t* r, uint32_t a) {
    asm volatile("ldmatrix.sync.aligned.m8n8.x4.shared.b16 {%0,%1,%2,%3}, [%4];"
                 : "=r"(r[0]), "=r"(r[1]), "=r"(r[2]), "=r"(r[3]) : "r"(a));
}
__device__ __forceinline__ void mma8(float* c, const uint32_t* a, uint32_t b0, uint32_t b1) {
    asm volatile(
        "mma.sync.aligned.m16n8k8.row.col.f32.tf32.tf32.f32 "
        "{%0,%1,%2,%3}, {%4,%5,%6,%7}, {%8,%9}, {%0,%1,%2,%3};"
        : "+f"(c[0]), "+f"(c[1]), "+f"(c[2]), "+f"(c[3])
        : "r"(a[0]), "r"(a[1]), "r"(a[2]), "r"(a[3]), "r"(b0), "r"(b1));
}

// ---------------- kernel 0: weight transposes + tf32 rounding ---------------
__global__ __launch_bounds__(256) void transpose_kernel(
    const float* __restrict__ w1, const float* __restrict__ w3,
    const float* __restrict__ w2)
{
    __shared__ float s[32][33];
    const int zz = blockIdx.z;
    const int tensor = zz >> 4, head = zz & 15;
    const float* src;
    float* dst;
    int R, C;
    if (tensor == 0)      { src = w1 + (size_t)head * HD * FH; dst = g_w1t + (size_t)head * FH * HD; R = HD; C = FH; }
    else if (tensor == 1) { src = w3 + (size_t)head * HD * FH; dst = g_w3t + (size_t)head * FH * HD; R = HD; C = FH; }
    else                  { src = w2 + (size_t)head * FH * HD; dst = g_w2t + (size_t)head * HD * FH; R = FH; C = HD; }

    const int r0 = blockIdx.y * 32, c0 = blockIdx.x * 32;
    if (r0 >= R || c0 >= C) return;
    const int tx = threadIdx.x & 31, ty = threadIdx.x >> 5;
#pragma unroll
    for (int j = 0; j < 4; j++)
        s[ty + 8 * j][tx] = src[(size_t)(r0 + ty + 8 * j) * C + c0 + tx];
    __syncthreads();
#pragma unroll
    for (int j = 0; j < 4; j++)
        dst[(size_t)(c0 + ty + 8 * j) * R + r0 + tx] = tf32r(s[tx][ty + 8 * j]);
}

// ---------------- kernel 1: rmsnorm1 -> headmix*mask + x -> rmsnorm2 --------
__global__ __launch_bounds__(512) void mix_kernel(
    const float* __restrict__ x,
    const float* __restrict__ n1w,
    const float* __restrict__ n2w,
    const float* __restrict__ mask)
{
    __shared__ float xn[16 * 272];

    const int b    = blockIdx.x;
    const int w    = threadIdx.x >> 5;
    const int lane = threadIdx.x & 31;

    const float* xb = x + ((size_t)b * NH + w) * HD;

    float v[8];
    float ss = 0.f;
#pragma unroll
    for (int q = 0; q < 8; q++) {
        v[q] = xb[lane + 32 * q];
        ss += v[q] * v[q];
    }
#pragma unroll
    for (int o = 16; o > 0; o >>= 1) ss += __shfl_xor_sync(0xffffffffu, ss, o);
    float rms = rsqrtf(ss * (1.f / HD) + 1e-6f);
#pragma unroll
    for (int q = 0; q < 8; q++) {
        int d = lane + 32 * q;
        xn[w * 272 + d] = v[q] * rms * n1w[d];
    }
    __syncthreads();

    float p[8];
    float ps = 0.f;
#pragma unroll
    for (int q = 0; q < 8; q++) {
        int d = lane + 32 * q;
        int j = d >> 4;
        int t = d & 15;
        float mixed = xn[j * 272 + (w << 4) + t] * mask[w * HD + d];
        float pv = mixed + v[q];
        p[q] = pv;
        ps += pv * pv;
    }
#pragma unroll
    for (int o = 16; o > 0; o >>= 1) ps += __shfl_xor_sync(0xffffffffu, ps, o);
    float rms2 = rsqrtf(ps * (1.f / HD) + 1e-6f);

    const size_t base = ((size_t)w * BATCH + b) * HD;   // head-major
#pragma unroll
    for (int q = 0; q < 8; q++) {
        int d = lane + 32 * q;
        g_p[base + d] = p[q];
        g_h[base + d] = tf32r(p[q] * rms2 * n2w[d]);
    }
}

// ---------------- kernel 2: fused  g_gate = tf32(silu(H@W1) * (H@W3)) -------
// CTA: M=128, N=64 (per matrix). warps 2(M) x 4(N); warp tile 64x16 per matrix.
// 3-stage cp.async pipeline, stage = A 16KB + B1 8KB + B3 8KB = 32KB.
__global__ __launch_bounds__(256, 2) void ffn1_kernel()
{
    constexpr int KT = HD / 32;   // 8
    extern __shared__ char smem[];
    const uint32_t sbase = smem_u32(smem);

    const int head = blockIdx.z;
    const int b0 = blockIdx.x * 128;
    const int n0 = blockIdx.y * 64;
    const int tid = threadIdx.x;

    const float* Ag  = g_h   + ((size_t)head * BATCH + b0) * HD;
    const float* B1g = g_w1t + ((size_t)head * FH + n0) * HD;
    const float* B3g = g_w3t + ((size_t)head * FH + n0) * HD;

    // loaders
    const int lrow = tid >> 3;
    const int lq   = tid & 7;
    uint32_t adst[4], bdst[2];
    const float* asrc[4];
    const float* b1src[2];
    const float* b3src[2];
#pragma unroll
    for (int t = 0; t < 4; t++) {
        int r = lrow + 32 * t;
        adst[t] = (uint32_t)r * 128 + ((uint32_t)(lq ^ (r & 7)) << 4);
        asrc[t] = Ag + (size_t)r * HD + lq * 4;
    }
#pragma unroll
    for (int t = 0; t < 2; t++) {
        int r = lrow + 32 * t;   // 0..63
        bdst[t] = (uint32_t)r * 128 + ((uint32_t)(lq ^ (r & 7)) << 4);
        b1src[t] = B1g + (size_t)r * HD + lq * 4;
        b3src[t] = B3g + (size_t)r * HD + lq * 4;
    }

    // compute mapping
    const int lane = tid & 31, warp = tid >> 5;
    const int wm = warp & 1, wn = warp >> 1;        // 2 x 4
    uint32_t aoff[4], boff;
    {
        int rb = wm * 64 + (lane & 15);
        int aq = lane >> 4;
#pragma unroll
        for (int mi = 0; mi < 4; mi++) {
            int r = rb + 16 * mi;
            aoff[mi] = (uint32_t)r * 128 + ((uint32_t)(aq ^ (r & 7)) << 4);
        }
        int r = wn * 16 + (lane & 7) + ((lane & 16) ? 8 : 0);
        int bq = (lane >> 3) & 1;
        boff = (uint32_t)r * 128 + ((uint32_t)(bq ^ (r & 7)) << 4);
    }

    float acc1[8][4], acc3[8][4];
#pragma unroll
    for (int i = 0; i < 8; i++)
#pragma unroll
        for (int j = 0; j < 4; j++) { acc1[i][j] = 0.f; acc3[i][j] = 0.f; }

    auto load_tile = [&](int kt, int buf) {
        uint32_t s = sbase + buf * 32768u;
#pragma unroll
        for (int t = 0; t < 4; t++) cp16(s + adst[t], asrc[t] + kt * 32);
#pragma unroll
        for (int t = 0; t < 2; t++) cp16(s + 16384u + bdst[t], b1src[t] + kt * 32);
#pragma unroll
        for (int t = 0; t < 2; t++) cp16(s + 24576u + bdst[t], b3src[t] + kt * 32);
    };

    load_tile(0, 0); cp_commit();
    load_tile(1, 1); cp_commit();

    for (int kt = 0; kt < KT; kt++) {
        if (kt == KT - 1) cp_wait<0>(); else cp_wait<1>();
        __syncthreads();
        uint32_t sA  = sbase + (uint32_t)(kt % 3) * 32768u;
        uint32_t sB1 = sA + 16384u;
        uint32_t sB3 = sA + 24576u;
#pragma unroll
        for (int ks = 0; ks < 4; ks++) {
            uint32_t xo = (uint32_t)ks << 5;
            uint32_t a[4][4], b1[4], b3[4];
#pragma unroll
            for (int mi = 0; mi < 4; mi++) ldsm4(a[mi], sA + (aoff[mi] ^ xo));
            ldsm4(b1, sB1 + (boff ^ xo));
            ldsm4(b3, sB3 + (boff ^ xo));
#pragma unroll
            for (int mi = 0; mi < 4; mi++)
#pragma unroll
                for (int nj = 0; nj < 2; nj++) {
                    mma8(acc1[mi * 2 + nj], a[mi], b1[nj * 2], b1[nj * 2 + 1]);
                    mma8(acc3[mi * 2 + nj], a[mi], b3[nj * 2], b3[nj * 2 + 1]);
                }
        }
        if (kt + 2 < KT) { load_tile(kt + 2, (kt + 2) % 3); cp_commit(); }
    }

    // epilogue: silu(acc1)*acc3 -> g_gate  (head-major [h][b][FH])
    const int g = lane >> 2, tg = lane & 3;
    float* c = g_gate + ((size_t)head * BATCH + b0) * FH + n0;
#pragma unroll
    for (int mi = 0; mi < 4; mi++) {
#pragma unroll
        for (int nj = 0; nj < 2; nj++) {
            float* d1 = acc1[mi * 2 + nj];
            float* d3 = acc3[mi * 2 + nj];
            int row = wm * 64 + mi * 16 + g;
            int col = wn * 16 + nj * 8 + 2 * tg;
#pragma unroll
            for (int h = 0; h < 2; h++) {
                float a0 = d1[2 * h], a1 = d1[2 * h + 1];
                float g0 = a0 / (1.f + __expf(-a0)) * d3[2 * h];
                float g1 = a1 / (1.f + __expf(-a1)) * d3[2 * h + 1];
                *(float2*)(c + (size_t)(row + 8 * h) * FH + col) =
                    make_float2(tf32r(g0), tf32r(g1));
            }
        }
    }
}

// ---------------- kernel 3: out = G @ W2 + P (token-major out) --------------
// CTA: 128x128, K=512. warps 2(M) x 4(N); warp tile 64x32. 3-stage pipeline.
__global__ __launch_bounds__(256, 2) void ffn2_kernel(float* __restrict__ outp)
{
    constexpr int KT = FH / 32;   // 16
    extern __shared__ char smem[];
    const uint32_t sbase = smem_u32(smem);

    const int head = blockIdx.z;
    const int b0 = blockIdx.x * 128;
    const int n0 = blockIdx.y * 128;
    const int tid = threadIdx.x;

    const float* Ag = g_gate + ((size_t)head * BATCH + b0) * FH;
    const float* Bg = g_w2t  + ((size_t)head * HD + n0) * FH;

    const int lrow = tid >> 3;
    const int lq   = tid & 7;
    uint32_t adst[4];
    const float* asrc[4];
    const float* bsrc[4];
#pragma unroll
    for (int t = 0; t < 4; t++) {
        int r = lrow + 32 * t;
        adst[t] = (uint32_t)r * 128 + ((uint32_t)(lq ^ (r & 7)) << 4);
        asrc[t] = Ag + (size_t)r * FH + lq * 4;
        bsrc[t] = Bg + (size_t)r * FH + lq * 4;
    }

    const int lane = tid & 31, warp = tid >> 5;
    const int wm = warp & 1, wn = warp >> 1;
    uint32_t aoff[4], boff[2];
    {
        int rb = wm * 64 + (lane & 15);
        int aq = lane >> 4;
#pragma unroll
        for (int mi = 0; mi < 4; mi++) {
            int r = rb + 16 * mi;
            aoff[mi] = (uint32_t)r * 128 + ((uint32_t)(aq ^ (r & 7)) << 4);
        }
#pragma unroll
        for (int p = 0; p < 2; p++) {
            int r = wn * 32 + p * 16 + (lane & 7) + ((lane & 16) ? 8 : 0);
            int bq = (lane >> 3) & 1;
            boff[p] = (uint32_t)r * 128 + ((uint32_t)(bq ^ (r & 7)) << 4);
        }
    }

    float acc[16][4];
#pragma unroll
    for (int i = 0; i < 16; i++)
#pragma unroll
        for (int j = 0; j < 4; j++) acc[i][j] = 0.f;

    auto load_tile = [&](int kt, int buf) {
        uint32_t s = sbase + buf * 32768u;
#pragma unroll
        for (int t = 0; t < 4; t++) cp16(s + adst[t], asrc[t] + kt * 32);
#pragma unroll
        for (int t = 0; t < 4; t++) cp16(s + 16384u + adst[t], bsrc[t] + kt * 32);
    };

    load_tile(0, 0); cp_commit();
    load_tile(1, 1); cp_commit();

    for (int kt = 0; kt < KT; kt++) {
        if (kt == KT - 1) cp_wait<0>(); else cp_wait<1>();
        __syncthreads();
        uint32_t sA = sbase + (uint32_t)(kt % 3) * 32768u;
        uint32_t sB = sA + 16384u;
#pragma unroll
        for (int ks = 0; ks < 4; ks++) {
            uint32_t xo = (uint32_t)ks << 5;
            uint32_t a[4][4], b[2][4];
#pragma unroll
            for (int mi = 0; mi < 4; mi++) ldsm4(a[mi], sA + (aoff[mi] ^ xo));
#pragma unroll
            for (int p = 0; p < 2; p++) ldsm4(b[p], sB + (boff[p] ^ xo));
#pragma unroll
            for (int mi = 0; mi < 4; mi++)
#pragma unroll
                for (int nj = 0; nj < 4; nj++)
                    mma8(acc[mi * 4 + nj], a[mi],
                         b[nj >> 1][(nj & 1) * 2], b[nj >> 1][(nj & 1) * 2 + 1]);
        }
        if (kt + 2 < KT) { load_tile(kt + 2, (kt + 2) % 3); cp_commit(); }
    }

    const int g = lane >> 2, tg = lane & 3;
    const float* px = g_p + ((size_t)head * BATCH + b0) * HD + n0;
#pragma unroll
    for (int mi = 0; mi < 4; mi++) {
#pragma unroll
        for (int nj = 0; nj < 4; nj++) {
            float* d = acc[mi * 4 + nj];
            int row = wm * 64 + mi * 16 + g;
            int col = wn * 32 + nj * 8 + 2 * tg;
#pragma unroll
            for (int h = 0; h < 2; h++) {
                float2 pv = *(const float2*)(px + (size_t)(row + 8 * h) * HD + col);
                float2 o = make_float2(d[2 * h] + pv.x, d[2 * h + 1] + pv.y);
                *(float2*)(outp + (size_t)(b0 + row + 8 * h) * NH * HD
                                + (size_t)head * HD + n0 + col) = o;
            }
        }
    }
}

// ---------------- launcher --------------------------------------------------
extern "C" void kernel_launch(void* const* d_in, const int* in_sizes, int n_in,
                              void* d_out, int out_size)
{
    const float* x    = (const float*)d_in[0];
    const float* n1w  = (const float*)d_in[1];
    const float* n2w  = (const float*)d_in[2];
    const float* w1   = (const float*)d_in[3];
    const float* w3   = (const float*)d_in[4];
    const float* w2   = (const float*)d_in[5];
    const float* mask = (const float*)d_in[6];
    float* out = (float*)d_out;

    cudaFuncSetAttribute(ffn1_kernel, cudaFuncAttributeMaxDynamicSharedMemorySize, 98304);
    cudaFuncSetAttribute(ffn2_kernel, cudaFuncAttributeMaxDynamicSharedMemorySize, 98304);

    transpose_kernel<<<dim3(16, 16, 48), 256>>>(w1, w3, w2);
    mix_kernel<<<BATCH, 512>>>(x, n1w, n2w, mask);
    ffn1_kernel<<<dim3(BATCH / 128, FH / 64, NH), 256, 98304>>>();
    ffn2_kernel<<<dim3(BATCH / 128, HD / 128, NH), 256, 98304>>>(out);
}